// round 4
// baseline (speedup 1.0000x reference)
#include <cuda_runtime.h>
#include <math.h>

#define NFFT   512
#define HOP    480
#define NBINS  257
#define BATCH  8
#define LSIG   88200
#define NT     184
#define NBLK   (BATCH * NT)   // 1472
#define NTHREADS 256          // 8 warps

__device__ float g_bark[NBINS];
__device__ float g_athv[NBINS];
__device__ float g_win[NFFT];
__device__ float g_partial[NBLK];
__device__ unsigned int g_count = 0;

// ---------------------------------------------------------------------------
// fp32 LUT init: bark, ATH, Hann window (one tiny launch, ~1us)
// ---------------------------------------------------------------------------
__global__ void init_kernel() {
    int i = threadIdx.x;             // 512 threads
    if (i < NFFT)
        g_win[i] = 0.5f * (1.0f - cospif((float)i * (1.0f / 256.0f)));
    if (i < NBINS) {
        float freq = (float)i * (44100.0f / 512.0f);
        float r = freq * (1.0f / 7500.0f);
        g_bark[i] = 13.0f * atanf(0.00076f * freq) + 3.5f * atanf(r * r);
        float fk = fmaxf(freq, 1e-6f) * 1e-3f;
        float ath_db = 3.64f * powf(fk, -0.8f)
                     - 6.5f * expf(-0.6f * (fk - 3.3f) * (fk - 3.3f))
                     + 0.001f * fk * fk * fk * fk;
        ath_db = fminf(fmaxf(ath_db, -100.0f), 100.0f);
        g_athv[i] = fmaxf(exp10f(ath_db * 0.1f), 1e-12f);
    }
}

// ---------------------------------------------------------------------------
// One 256-thread block per (b,t) frame.
// ---------------------------------------------------------------------------
__global__ __launch_bounds__(NTHREADS) void pam_frame_kernel(
    const float* __restrict__ pred, const float* __restrict__ tgt,
    float* __restrict__ out)
{
    __shared__ float2 Z[NFFT];       // packed complex frame (pred + i*target)
    __shared__ float2 Wt[NFFT];      // twiddle tree: Wt[half+pos] = e^{-i pi pos/half}
    __shared__ float dbv[NBINS];
    __shared__ float sB[256];
    __shared__ float sSuf[256];
    __shared__ float awtot[8], bwtot[8], redw[8];
    __shared__ int s_last;

    const int t    = blockIdx.x;
    const int b    = blockIdx.y;
    const int tid  = threadIdx.x;
    const int lane = tid & 31;
    const int wrp  = tid >> 5;

    const float* xp = pred + b * LSIG;
    const float* xt = tgt  + b * LSIG;

    // ---- twiddle tree fill: entries m = tid and tid+256 (skip m==0) ----
    #pragma unroll
    for (int h = 0; h < 2; h++) {
        int m = tid + h * 256;
        if (m > 0) {
            int s = 31 - __clz(m);                     // floor log2(m)
            int pos = m - (1 << s);
            float inv = __int_as_float((127 - s) << 23);  // exact 2^-s
            float sw, cw;
            sincospif((float)pos * inv, &sw, &cw);     // angle = pi*pos/half
            Wt[m] = make_float2(cw, sw);
        }
    }

    // ---- load frame (reflect pad, windowed) bit-reversed into Z ----
    #pragma unroll
    for (int h = 0; h < 2; h++) {
        int n = tid + h * 256;
        int j = t * HOP + n - (NFFT / 2);
        if (j < 0) j = -j;
        if (j >= LSIG) j = 2 * LSIG - 2 - j;
        float w = g_win[n];
        int rn = (int)(__brev((unsigned)n) >> 23);
        Z[rn] = make_float2(xp[j] * w, xt[j] * w);
    }
    __syncthreads();

    // ---- 9 radix-2 DIT stages; per-stage twiddles from the shared tree ----
    #pragma unroll
    for (int s = 0; s < 9; s++) {
        int half = 1 << s;
        int pos  = tid & (half - 1);
        int i0 = ((tid >> s) << (s + 1)) + pos;
        int i1 = i0 + half;
        float2 w = Wt[half + pos];
        float2 a = Z[i0], v = Z[i1];
        float tr = w.x * v.x + w.y * v.y;   // (cw - i*sw) * v
        float ti = w.x * v.y - w.y * v.x;
        Z[i0] = make_float2(a.x + tr, a.y + ti);
        Z[i1] = make_float2(a.x - tr, a.y - ti);
        __syncthreads();
    }

    // ---- unpack both real spectra; thread 255 also owns bin 256 ----
    float2 zk = Z[tid];
    float2 zc = Z[(NFFT - tid) & (NFFT - 1)];
    float spr = zk.x + zc.x, spi = zk.y - zc.y;
    float str = zk.y + zc.y, sti = zc.x - zk.x;
    float powP = 0.25f * (spr * spr + spi * spi) + 1e-12f;
    float powT = 0.25f * (str * str + sti * sti) + 1e-12f;
    float mydb = 10.0f * log10f(powT);
    dbv[tid] = mydb;
    float mybark = g_bark[tid];
    float myath  = g_athv[tid];

    float powP6 = 0.f, powT6 = 0.f;      // bin-256 state (thread 255 only)
    if (tid == 255) {
        float2 z6 = Z[256];
        powP6 = z6.x * z6.x + 1e-12f;
        powT6 = z6.y * z6.y + 1e-12f;
        dbv[256] = 10.0f * log10f(powT6);
    }
    __syncthreads();

    // ---- tonal peaks (bins 1..255), log-domain masker terms ----
    float aval = -1e30f, bval = -1e30f;
    if (tid >= 1 && tid <= 255) {
        bool tonal = (mydb > dbv[tid - 1]) && (mydb > dbv[tid + 1]) && (mydb >= -40.0f);
        if (tonal) {
            float L = mydb * 0.1f;
            aval = L + 1.7f * mybark;
            bval = L - 2.7f * mybark;
        }
    }
    sB[tid] = bval;

    // warp inclusive prefix-max of aval (thread order == bin order)
    float av = aval;
    #pragma unroll
    for (int off = 1; off < 32; off <<= 1) {
        float o = __shfl_up_sync(0xffffffffu, av, off);
        if (lane >= off) av = fmaxf(av, o);
    }
    if (lane == 31) awtot[wrp] = av;
    __syncthreads();                     // sB written, awtot done

    // reversed-order scan of bval -> suffix-max
    const int ri = 255 - tid;
    float bv = sB[ri];
    #pragma unroll
    for (int off = 1; off < 32; off <<= 1) {
        float o = __shfl_up_sync(0xffffffffu, bv, off);
        if (lane >= off) bv = fmaxf(bv, o);
    }
    if (lane == 31) bwtot[wrp] = bv;
    __syncthreads();

    // combine warp totals; publish suffix-max
    float aoff = -1e30f, boff = -1e30f;
    #pragma unroll
    for (int j = 0; j < 7; j++) {
        if (j < wrp) {
            aoff = fmaxf(aoff, awtot[j]);
            boff = fmaxf(boff, bwtot[j]);
        }
    }
    float Apre = fmaxf(av, aoff);        // prefix-max at bin tid
    sSuf[ri] = fmaxf(bv, boff);          // suffix-max at bin ri
    __syncthreads();

    // ---- masking, weights, error ----
    float Bsuf = sSuf[tid];
    float mlog = fmaxf(Apre - 1.7f * mybark, Bsuf + 2.7f * mybark);
    float masking = exp2f(mlog * 3.3219280948873623f);   // 10^mlog
    float combined = masking + myath;
    float w  = log10f(powT / (combined + 1e-12f) + 1.0f);
    float mp = sqrtf(powP + 1e-12f);
    float mt = sqrtf(powT + 1e-12f);
    float d  = mp - mt;
    float contrib = w * d * d;

    if (tid == 255) {                    // bin 256: never tonal, only consumes
        float bark6 = g_bark[256];
        float ath6  = g_athv[256];
        float mlog6 = Apre - 1.7f * bark6;        // B-side is -inf
        float mask6 = exp2f(mlog6 * 3.3219280948873623f);
        float comb6 = mask6 + ath6;
        float w6  = log10f(powT6 / (comb6 + 1e-12f) + 1.0f);
        float mp6 = sqrtf(powP6 + 1e-12f);
        float mt6 = sqrtf(powT6 + 1e-12f);
        float d6  = mp6 - mt6;
        contrib += w6 * d6 * d6;
    }

    // ---- block reduction ----
    float v = contrib;
    #pragma unroll
    for (int off = 16; off > 0; off >>= 1)
        v += __shfl_down_sync(0xffffffffu, v, off);
    if (lane == 0) redw[wrp] = v;
    __syncthreads();
    if (tid == 0) {
        float s = redw[0];
        #pragma unroll
        for (int j = 1; j < 8; j++) s += redw[j];
        g_partial[b * NT + t] = s;
    }

    // ---- last block: deterministic global reduction ----
    __threadfence();
    if (tid == 0) {
        unsigned r = atomicAdd(&g_count, 1u);
        s_last = (r == NBLK - 1) ? 1 : 0;
    }
    __syncthreads();
    if (s_last) {
        float s = 0.0f;
        for (int i = tid; i < NBLK; i += NTHREADS) s += g_partial[i];
        #pragma unroll
        for (int off = 16; off > 0; off >>= 1)
            s += __shfl_down_sync(0xffffffffu, s, off);
        if (lane == 0) redw[wrp] = s;
        __syncthreads();
        if (tid == 0) {
            float s2 = redw[0];
            #pragma unroll
            for (int j = 1; j < 8; j++) s2 += redw[j];
            out[0] = s2 * (1.0f / (float)(BATCH * NBINS * NT));
            g_count = 0;                 // reset for next graph replay
        }
    }
}

extern "C" void kernel_launch(void* const* d_in, const int* in_sizes, int n_in,
                              void* d_out, int out_size) {
    const float* pred = (const float*)d_in[0];
    const float* tgt  = (const float*)d_in[1];
    float* out = (float*)d_out;
    init_kernel<<<1, 512>>>();
    dim3 grid(NT, BATCH);
    pam_frame_kernel<<<grid, NTHREADS>>>(pred, tgt, out);
}

// round 6
// speedup vs baseline: 1.5529x; 1.5529x over previous
#include <cuda_runtime.h>
#include <math.h>

#define NFFT   512
#define HOP    480
#define NBINS  257
#define BATCH  8
#define LSIG   88200
#define NT     184
#define NBLKS  (BATCH * NT / 2)   // 736 blocks, 2 frames each
#define L2_10  3.3219280948873623f

__device__ float g_partial[NBLKS];
__device__ unsigned int g_count = 0;

__device__ __forceinline__ float2 cadd(float2 a, float2 b) { return make_float2(a.x + b.x, a.y + b.y); }
__device__ __forceinline__ float2 csub(float2 a, float2 b) { return make_float2(a.x - b.x, a.y - b.y); }
__device__ __forceinline__ float2 cmul(float2 a, float2 b) {
    return make_float2(fmaf(a.x, b.x, -a.y * b.y), fmaf(a.x, b.y, a.y * b.x));
}

// 8-point DFT, natural in/out order: y_r = sum_m x_m * e^{-2pi i rm/8}
__device__ __forceinline__ void dft8(float2* x) {
    const float C = 0.70710678118654752f;
    float2 a0 = cadd(x[0], x[4]), a4 = csub(x[0], x[4]);
    float2 a2 = cadd(x[2], x[6]), a6 = csub(x[2], x[6]);
    float2 a1 = cadd(x[1], x[5]), a5 = csub(x[1], x[5]);
    float2 a3 = cadd(x[3], x[7]), a7 = csub(x[3], x[7]);
    float2 b0 = cadd(a0, a2), b2 = csub(a0, a2);
    float2 b1 = cadd(a1, a3), b3 = csub(a1, a3);
    float2 b4 = make_float2(a4.x + a6.y, a4.y - a6.x);  // a4 - i a6
    float2 b6 = make_float2(a4.x - a6.y, a4.y + a6.x);  // a4 + i a6
    float2 b5 = make_float2(a5.x + a7.y, a5.y - a7.x);
    float2 b7 = make_float2(a5.x - a7.y, a5.y + a7.x);
    x[0] = cadd(b0, b1);  x[4] = csub(b0, b1);
    x[2] = make_float2(b2.x + b3.y, b2.y - b3.x);       // b2 - i b3
    x[6] = make_float2(b2.x - b3.y, b2.y + b3.x);
    float2 t5 = make_float2(C * (b5.x + b5.y), C * (b5.y - b5.x));   // w8 * b5
    x[1] = cadd(b4, t5);  x[5] = csub(b4, t5);
    float2 t7 = make_float2(C * (b7.y - b7.x), -C * (b7.x + b7.y));  // w8^3 * b7
    x[3] = cadd(b6, t7);  x[7] = csub(b6, t7);
}

#define PHYS(i) ((i) + ((i) >> 3))

__global__ __launch_bounds__(128) void pam_kernel(
    const float* __restrict__ pred, const float* __restrict__ tgt,
    float* __restrict__ out)
{
    __shared__ float2 Zs[2][576];               // padded 512-pt complex, per frame
    __shared__ float wins[512];
    __shared__ float barks[NBINS], aths[NBINS];
    __shared__ __align__(16) float dbvs[2][260];
    __shared__ float sAg[2], sBg[2];
    __shared__ float redw[4];
    __shared__ int   s_last;

    const int tid  = threadIdx.x;
    const int sub  = tid >> 6;             // frame within block (0/1)
    const int j    = tid & 63;             // thread within frame
    const int lane = tid & 31;
    const int wrp  = tid >> 5;             // 0..3
    const int fw   = wrp & 1;              // warp within frame

    const int t = 2 * blockIdx.x + sub;
    const int b = blockIdx.y;

    // ---- block-shared LUTs (both frames use identical tables) ----
    #pragma unroll
    for (int h = 0; h < 4; h++) {
        int i = tid + h * 128;
        wins[i] = 0.5f * (1.0f - cospif((float)i * (1.0f / 256.0f)));
    }
    for (int i = tid; i < NBINS; i += 128) {
        float freq = (float)i * (44100.0f / 512.0f);
        float r = freq * (1.0f / 7500.0f);
        barks[i] = 13.0f * atanf(0.00076f * freq) + 3.5f * atanf(r * r);
        float fk = fmaxf(freq, 1e-6f) * 1e-3f;
        float ath_db = 3.64f * powf(fk, -0.8f)
                     - 6.5f * expf(-0.6f * (fk - 3.3f) * (fk - 3.3f))
                     + 0.001f * fk * fk * fk * fk;
        ath_db = fminf(fmaxf(ath_db, -100.0f), 100.0f);
        aths[i] = fmaxf(exp10f(ath_db * 0.1f), 1e-12f);
    }
    __syncthreads();

    // ---- load frame, natural order, windowed, reflect-padded ----
    const float* xp = pred + b * LSIG;
    const float* xt = tgt  + b * LSIG;
    const int tb = t * HOP - (NFFT / 2);
    #pragma unroll
    for (int h = 0; h < 8; h++) {
        int n = h * 64 + j;
        int g = tb + n;
        if (g < 0) g = -g;
        if (g >= LSIG) g = 2 * LSIG - 2 - g;
        float w = wins[n];
        Zs[sub][PHYS(n)] = make_float2(xp[g] * w, xt[g] * w);
    }
    __syncthreads();

    // ---- pass 0: Lc=512, butterfly stride 64, twiddle W512^(j*r) ----
    {
        float2 x[8];
        #pragma unroll
        for (int m = 0; m < 8; m++) { int i = j + (m << 6); x[m] = Zs[sub][PHYS(i)]; }
        dft8(x);
        float s, c; sincospif((float)j * (1.0f / 256.0f), &s, &c);
        float2 w = make_float2(c, -s), wc = w;
        #pragma unroll
        for (int r = 1; r < 8; r++) { x[r] = cmul(x[r], wc); wc = cmul(wc, w); }
        #pragma unroll
        for (int r = 0; r < 8; r++) { int i = j + (r << 6); Zs[sub][PHYS(i)] = x[r]; }
    }
    __syncthreads();

    // ---- pass 1: Lc=64, stride 8, twiddle W64^(p*r) ----
    {
        int p = j & 7;
        int base = ((j >> 3) << 6) + p;
        float2 x[8];
        #pragma unroll
        for (int m = 0; m < 8; m++) { int i = base + (m << 3); x[m] = Zs[sub][PHYS(i)]; }
        dft8(x);
        float s, c; sincospif((float)p * (1.0f / 32.0f), &s, &c);
        float2 w = make_float2(c, -s), wc = w;
        #pragma unroll
        for (int r = 1; r < 8; r++) { x[r] = cmul(x[r], wc); wc = cmul(wc, w); }
        #pragma unroll
        for (int r = 0; r < 8; r++) { int i = base + (r << 3); Zs[sub][PHYS(i)] = x[r]; }
    }
    __syncthreads();

    // ---- pass 2: Lc=8, contiguous, no twiddle (phys = 9j+m) ----
    {
        float2 x[8];
        #pragma unroll
        for (int m = 0; m < 8; m++) x[m] = Zs[sub][9 * j + m];
        dft8(x);
        #pragma unroll
        for (int m = 0; m < 8; m++) Zs[sub][9 * j + m] = x[m];
    }
    __syncthreads();

    // ---- unpack both real spectra; bins 4j..4j+3 per thread ----
    float pp[4], pt[4], db[4];
    #pragma unroll
    for (int i = 0; i < 4; i++) {
        int k  = 4 * j + i;
        int pk = ((k & 7) << 6) | (k & 56) | (k >> 6);          // digit-reversed pos
        int kc = (NFFT - k) & (NFFT - 1);
        int pc = ((kc & 7) << 6) | (kc & 56) | (kc >> 6);
        float2 zk = Zs[sub][PHYS(pk)];
        float2 zc = Zs[sub][PHYS(pc)];
        float spr = zk.x + zc.x, spi = zk.y - zc.y;
        float str = zk.y + zc.y, sti = zc.x - zk.x;
        pp[i] = 0.25f * (spr * spr + spi * spi) + 1e-12f;
        pt[i] = 0.25f * (str * str + sti * sti) + 1e-12f;
        db[i] = 10.0f * log10f(pt[i]);
    }
    *(float4*)&dbvs[sub][4 * j] = make_float4(db[0], db[1], db[2], db[3]);

    float pp6 = 0.f, pt6 = 0.f;
    if (j == 63) {                        // bin 256 lives at digit-reversed pos 4
        float2 z6 = Zs[sub][PHYS(4)];
        pp6 = z6.x * z6.x + 1e-12f;
        pt6 = z6.y * z6.y + 1e-12f;
        dbvs[sub][256] = 10.0f * log10f(pt6);
    }
    __syncthreads();

    // ---- tonal detection + log-domain masker terms ----
    float a[4], bb[4], bk4[4];
    #pragma unroll
    for (int i = 0; i < 4; i++) {
        int k = 4 * j + i;
        float dbm = db[i];
        float dprev = (i == 0) ? ((j == 0) ? 3.4e38f : dbvs[sub][4 * j - 1]) : db[i - 1];
        float dnext = (i == 3) ? dbvs[sub][k + 1] : db[i + 1];
        bool tonal = (k >= 1) && (dbm > dprev) && (dbm > dnext) && (dbm >= -40.0f);
        float bk = barks[k];
        bk4[i] = bk;
        float L = dbm * 0.1f;
        a[i]  = tonal ? (L + 1.7f * bk) : -1e30f;
        bb[i] = tonal ? (L - 2.7f * bk) : -1e30f;
    }

    // local prefix/suffix + thread aggregates
    float pa0 = a[0];
    float pa1 = fmaxf(pa0, a[1]);
    float pa2 = fmaxf(pa1, a[2]);
    float pa3 = fmaxf(pa2, a[3]);
    float sb3 = bb[3];
    float sb2 = fmaxf(sb3, bb[2]);
    float sb1 = fmaxf(sb2, bb[1]);
    float sb0 = fmaxf(sb1, bb[0]);

    // warp inclusive scan (forward) of thread aggregate pa3
    float inc = pa3;
    #pragma unroll
    for (int off = 1; off < 32; off <<= 1) {
        float o = __shfl_up_sync(0xffffffffu, inc, off);
        if (lane >= off) inc = fmaxf(inc, o);
    }
    float exA = __shfl_up_sync(0xffffffffu, inc, 1);
    if (lane == 0) exA = -1e30f;
    if (fw == 0 && lane == 31) sAg[sub] = inc;

    // warp reverse-inclusive scan of thread aggregate sb0
    float rinc = sb0;
    #pragma unroll
    for (int off = 1; off < 32; off <<= 1) {
        float o = __shfl_down_sync(0xffffffffu, rinc, off);
        if (lane + off < 32) rinc = fmaxf(rinc, o);
    }
    float exB = __shfl_down_sync(0xffffffffu, rinc, 1);
    if (lane == 31) exB = -1e30f;
    if (fw == 1 && lane == 0) sBg[sub] = rinc;
    __syncthreads();

    if (fw == 1) exA = fmaxf(exA, sAg[sub]);   // warp1 sees warp0's total
    if (fw == 0) exB = fmaxf(exB, sBg[sub]);   // warp0 sees warp1's total

    // ---- per-bin masking, weights, error ----
    float Apre[4] = { fmaxf(exA, pa0), fmaxf(exA, pa1), fmaxf(exA, pa2), fmaxf(exA, pa3) };
    float Bsuf[4] = { fmaxf(exB, sb0), fmaxf(exB, sb1), fmaxf(exB, sb2), fmaxf(exB, sb3) };

    float contrib = 0.0f;
    #pragma unroll
    for (int i = 0; i < 4; i++) {
        float bk = bk4[i];
        float mlog = fmaxf(Apre[i] - 1.7f * bk, Bsuf[i] + 2.7f * bk);
        float masking = exp2f(mlog * L2_10);
        float combined = masking + aths[4 * j + i];
        float w  = log10f(pt[i] / (combined + 1e-12f) + 1.0f);
        float mp = sqrtf(pp[i]);
        float mt = sqrtf(pt[i]);
        float d  = mp - mt;
        contrib += w * d * d;
    }
    if (j == 63) {                          // bin 256: never tonal, consumes A-side only
        float bk = barks[256];
        float mlog = Apre[3] - 1.7f * bk;
        float masking = exp2f(mlog * L2_10);
        float combined = masking + aths[256];
        float w  = log10f(pt6 / (combined + 1e-12f) + 1.0f);
        float mp = sqrtf(pp6);
        float mt = sqrtf(pt6);
        float d  = mp - mt;
        contrib += w * d * d;
    }

    // ---- block reduction (both frames into one partial) ----
    float v = contrib;
    #pragma unroll
    for (int off = 16; off > 0; off >>= 1)
        v += __shfl_down_sync(0xffffffffu, v, off);
    if (lane == 0) redw[wrp] = v;
    __syncthreads();
    const int bid = blockIdx.y * (NT / 2) + blockIdx.x;
    if (tid == 0)
        g_partial[bid] = redw[0] + redw[1] + redw[2] + redw[3];

    // ---- last block: deterministic global reduction ----
    __threadfence();
    if (tid == 0) {
        unsigned r = atomicAdd(&g_count, 1u);
        s_last = (r == NBLKS - 1) ? 1 : 0;
    }
    __syncthreads();
    if (s_last) {
        float s = 0.0f;
        for (int i = tid; i < NBLKS; i += 128) s += g_partial[i];
        #pragma unroll
        for (int off = 16; off > 0; off >>= 1)
            s += __shfl_down_sync(0xffffffffu, s, off);
        if (lane == 0) redw[wrp] = s;
        __syncthreads();
        if (tid == 0) {
            out[0] = (redw[0] + redw[1] + redw[2] + redw[3])
                   * (1.0f / (float)(BATCH * NBINS * NT));
            g_count = 0;                    // reset for next graph replay
        }
    }
}

extern "C" void kernel_launch(void* const* d_in, const int* in_sizes, int n_in,
                              void* d_out, int out_size) {
    const float* pred = (const float*)d_in[0];
    const float* tgt  = (const float*)d_in[1];
    float* out = (float*)d_out;
    dim3 grid(NT / 2, BATCH);
    pam_kernel<<<grid, 128>>>(pred, tgt, out);
}

// round 7
// speedup vs baseline: 1.7070x; 1.0993x over previous
#include <cuda_runtime.h>
#include <math.h>

#define NFFT   512
#define HOP    480
#define NBINS  257
#define BATCH  8
#define LSIG   88200
#define NT     184
#define NFR    4                      // frames per block
#define NTHREADS 256
#define NBLKS  (BATCH * NT / NFR)     // 368 blocks
#define L2_10  3.3219280948873623f

__device__ float g_partial[NBLKS];
__device__ unsigned int g_count = 0;

__device__ __forceinline__ float2 cadd(float2 a, float2 b) { return make_float2(a.x + b.x, a.y + b.y); }
__device__ __forceinline__ float2 csub(float2 a, float2 b) { return make_float2(a.x - b.x, a.y - b.y); }
__device__ __forceinline__ float2 cmul(float2 a, float2 b) {
    return make_float2(fmaf(a.x, b.x, -a.y * b.y), fmaf(a.x, b.y, a.y * b.x));
}

// 8-point DFT, natural in/out order: y_r = sum_m x_m * e^{-2pi i rm/8}
__device__ __forceinline__ void dft8(float2* x) {
    const float C = 0.70710678118654752f;
    float2 a0 = cadd(x[0], x[4]), a4 = csub(x[0], x[4]);
    float2 a2 = cadd(x[2], x[6]), a6 = csub(x[2], x[6]);
    float2 a1 = cadd(x[1], x[5]), a5 = csub(x[1], x[5]);
    float2 a3 = cadd(x[3], x[7]), a7 = csub(x[3], x[7]);
    float2 b0 = cadd(a0, a2), b2 = csub(a0, a2);
    float2 b1 = cadd(a1, a3), b3 = csub(a1, a3);
    float2 b4 = make_float2(a4.x + a6.y, a4.y - a6.x);  // a4 - i a6
    float2 b6 = make_float2(a4.x - a6.y, a4.y + a6.x);  // a4 + i a6
    float2 b5 = make_float2(a5.x + a7.y, a5.y - a7.x);
    float2 b7 = make_float2(a5.x - a7.y, a5.y + a7.x);
    x[0] = cadd(b0, b1);  x[4] = csub(b0, b1);
    x[2] = make_float2(b2.x + b3.y, b2.y - b3.x);       // b2 - i b3
    x[6] = make_float2(b2.x - b3.y, b2.y + b3.x);
    float2 t5 = make_float2(C * (b5.x + b5.y), C * (b5.y - b5.x));   // w8 * b5
    x[1] = cadd(b4, t5);  x[5] = csub(b4, t5);
    float2 t7 = make_float2(C * (b7.y - b7.x), -C * (b7.x + b7.y));  // w8^3 * b7
    x[3] = cadd(b6, t7);  x[7] = csub(b6, t7);
}

#define PHYS(i) ((i) + ((i) >> 3))

__global__ __launch_bounds__(NTHREADS) void pam_kernel(
    const float* __restrict__ pred, const float* __restrict__ tgt,
    float* __restrict__ out)
{
    __shared__ float2 Zs[NFR][576];             // padded 512-pt complex, per frame
    __shared__ float wins[512];
    __shared__ float barks[NBINS], aths[NBINS];
    __shared__ __align__(16) float dbvs[NFR][260];
    __shared__ float sAg[NFR], sBg[NFR];
    __shared__ float redw[8];
    __shared__ int   s_last;

    const int tid  = threadIdx.x;
    const int sub  = tid >> 6;             // frame within block (0..3)
    const int j    = tid & 63;             // thread within frame
    const int lane = tid & 31;
    const int wrp  = tid >> 5;             // 0..7
    const int fw   = wrp & 1;              // warp within frame

    const int t = NFR * blockIdx.x + sub;
    const int b = blockIdx.y;

    // ---- block-shared LUTs (all 4 frames share the same tables) ----
    #pragma unroll
    for (int h = 0; h < 2; h++) {
        int i = tid + h * 256;
        wins[i] = 0.5f * (1.0f - cospif((float)i * (1.0f / 256.0f)));
    }
    for (int i = tid; i < NBINS; i += NTHREADS) {
        float freq = (float)i * (44100.0f / 512.0f);
        float r = freq * (1.0f / 7500.0f);
        barks[i] = 13.0f * atanf(0.00076f * freq) + 3.5f * atanf(r * r);
        float fk = fmaxf(freq, 1e-6f) * 1e-3f;
        float ath_db = 3.64f * __powf(fk, -0.8f)
                     - 6.5f * __expf(-0.6f * (fk - 3.3f) * (fk - 3.3f))
                     + 0.001f * fk * fk * fk * fk;
        ath_db = fminf(fmaxf(ath_db, -100.0f), 100.0f);
        aths[i] = fmaxf(exp2f(ath_db * (0.1f * L2_10)), 1e-12f);
    }
    __syncthreads();

    // ---- load frame, natural order, windowed, reflect-padded ----
    const float* xp = pred + b * LSIG;
    const float* xt = tgt  + b * LSIG;
    const int tb = t * HOP - (NFFT / 2);
    #pragma unroll
    for (int h = 0; h < 8; h++) {
        int n = h * 64 + j;
        int g = tb + n;
        if (g < 0) g = -g;
        if (g >= LSIG) g = 2 * LSIG - 2 - g;
        float w = wins[n];
        Zs[sub][PHYS(n)] = make_float2(xp[g] * w, xt[g] * w);
    }
    __syncthreads();

    // ---- pass 0: Lc=512, butterfly stride 64, twiddle W512^(j*r) ----
    {
        float2 x[8];
        #pragma unroll
        for (int m = 0; m < 8; m++) { int i = j + (m << 6); x[m] = Zs[sub][PHYS(i)]; }
        dft8(x);
        float s, c; sincospif((float)j * (1.0f / 256.0f), &s, &c);
        float2 w = make_float2(c, -s), wc = w;
        #pragma unroll
        for (int r = 1; r < 8; r++) { x[r] = cmul(x[r], wc); wc = cmul(wc, w); }
        #pragma unroll
        for (int r = 0; r < 8; r++) { int i = j + (r << 6); Zs[sub][PHYS(i)] = x[r]; }
    }
    __syncthreads();

    // ---- pass 1: Lc=64, stride 8, twiddle W64^(p*r) ----
    {
        int p = j & 7;
        int base = ((j >> 3) << 6) + p;
        float2 x[8];
        #pragma unroll
        for (int m = 0; m < 8; m++) { int i = base + (m << 3); x[m] = Zs[sub][PHYS(i)]; }
        dft8(x);
        float s, c; sincospif((float)p * (1.0f / 32.0f), &s, &c);
        float2 w = make_float2(c, -s), wc = w;
        #pragma unroll
        for (int r = 1; r < 8; r++) { x[r] = cmul(x[r], wc); wc = cmul(wc, w); }
        #pragma unroll
        for (int r = 0; r < 8; r++) { int i = base + (r << 3); Zs[sub][PHYS(i)] = x[r]; }
    }
    __syncthreads();

    // ---- pass 2: Lc=8, contiguous, no twiddle (phys = 9j+m) ----
    {
        float2 x[8];
        #pragma unroll
        for (int m = 0; m < 8; m++) x[m] = Zs[sub][9 * j + m];
        dft8(x);
        #pragma unroll
        for (int m = 0; m < 8; m++) Zs[sub][9 * j + m] = x[m];
    }
    __syncthreads();

    // ---- unpack both real spectra; bins 4j..4j+3 per thread ----
    float pp[4], pt[4], db[4];
    #pragma unroll
    for (int i = 0; i < 4; i++) {
        int k  = 4 * j + i;
        int pk = ((k & 7) << 6) | (k & 56) | (k >> 6);          // digit-reversed pos
        int kc = (NFFT - k) & (NFFT - 1);
        int pc = ((kc & 7) << 6) | (kc & 56) | (kc >> 6);
        float2 zk = Zs[sub][PHYS(pk)];
        float2 zc = Zs[sub][PHYS(pc)];
        float spr = zk.x + zc.x, spi = zk.y - zc.y;
        float str = zk.y + zc.y, sti = zc.x - zk.x;
        pp[i] = 0.25f * (spr * spr + spi * spi) + 1e-12f;
        pt[i] = 0.25f * (str * str + sti * sti) + 1e-12f;
        db[i] = 10.0f * log10f(pt[i]);
    }
    *(float4*)&dbvs[sub][4 * j] = make_float4(db[0], db[1], db[2], db[3]);

    float pp6 = 0.f, pt6 = 0.f;
    if (j == 63) {                        // bin 256 lives at digit-reversed pos 4
        float2 z6 = Zs[sub][PHYS(4)];
        pp6 = z6.x * z6.x + 1e-12f;
        pt6 = z6.y * z6.y + 1e-12f;
        dbvs[sub][256] = 10.0f * log10f(pt6);
    }
    __syncthreads();

    // ---- tonal detection + log-domain masker terms ----
    float a[4], bb[4], bk4[4];
    #pragma unroll
    for (int i = 0; i < 4; i++) {
        int k = 4 * j + i;
        float dbm = db[i];
        float dprev = (i == 0) ? ((j == 0) ? 3.4e38f : dbvs[sub][4 * j - 1]) : db[i - 1];
        float dnext = (i == 3) ? dbvs[sub][k + 1] : db[i + 1];
        bool tonal = (k >= 1) && (dbm > dprev) && (dbm > dnext) && (dbm >= -40.0f);
        float bk = barks[k];
        bk4[i] = bk;
        float L = dbm * 0.1f;
        a[i]  = tonal ? (L + 1.7f * bk) : -1e30f;
        bb[i] = tonal ? (L - 2.7f * bk) : -1e30f;
    }

    // local prefix/suffix + thread aggregates
    float pa0 = a[0];
    float pa1 = fmaxf(pa0, a[1]);
    float pa2 = fmaxf(pa1, a[2]);
    float pa3 = fmaxf(pa2, a[3]);
    float sb3 = bb[3];
    float sb2 = fmaxf(sb3, bb[2]);
    float sb1 = fmaxf(sb2, bb[1]);
    float sb0 = fmaxf(sb1, bb[0]);

    // warp inclusive scan (forward) of thread aggregate pa3
    float inc = pa3;
    #pragma unroll
    for (int off = 1; off < 32; off <<= 1) {
        float o = __shfl_up_sync(0xffffffffu, inc, off);
        if (lane >= off) inc = fmaxf(inc, o);
    }
    float exA = __shfl_up_sync(0xffffffffu, inc, 1);
    if (lane == 0) exA = -1e30f;
    if (fw == 0 && lane == 31) sAg[sub] = inc;

    // warp reverse-inclusive scan of thread aggregate sb0
    float rinc = sb0;
    #pragma unroll
    for (int off = 1; off < 32; off <<= 1) {
        float o = __shfl_down_sync(0xffffffffu, rinc, off);
        if (lane + off < 32) rinc = fmaxf(rinc, o);
    }
    float exB = __shfl_down_sync(0xffffffffu, rinc, 1);
    if (lane == 31) exB = -1e30f;
    if (fw == 1 && lane == 0) sBg[sub] = rinc;
    __syncthreads();

    if (fw == 1) exA = fmaxf(exA, sAg[sub]);   // back warp sees front warp's total
    if (fw == 0) exB = fmaxf(exB, sBg[sub]);   // front warp sees back warp's total

    // ---- per-bin masking, weights, error ----
    float Apre[4] = { fmaxf(exA, pa0), fmaxf(exA, pa1), fmaxf(exA, pa2), fmaxf(exA, pa3) };
    float Bsuf[4] = { fmaxf(exB, sb0), fmaxf(exB, sb1), fmaxf(exB, sb2), fmaxf(exB, sb3) };

    float contrib = 0.0f;
    #pragma unroll
    for (int i = 0; i < 4; i++) {
        float bk = bk4[i];
        float mlog = fmaxf(Apre[i] - 1.7f * bk, Bsuf[i] + 2.7f * bk);
        float masking = exp2f(mlog * L2_10);
        float combined = masking + aths[4 * j + i];
        float w  = __log10f(pt[i] / (combined + 1e-12f) + 1.0f);
        float mp = sqrtf(pp[i]);
        float mt = sqrtf(pt[i]);
        float d  = mp - mt;
        contrib += w * d * d;
    }
    if (j == 63) {                          // bin 256: never tonal, consumes A-side only
        float bk = barks[256];
        float mlog = Apre[3] - 1.7f * bk;
        float masking = exp2f(mlog * L2_10);
        float combined = masking + aths[256];
        float w  = __log10f(pt6 / (combined + 1e-12f) + 1.0f);
        float mp = sqrtf(pp6);
        float mt = sqrtf(pt6);
        float d  = mp - mt;
        contrib += w * d * d;
    }

    // ---- block reduction (all 4 frames into one partial) ----
    float v = contrib;
    #pragma unroll
    for (int off = 16; off > 0; off >>= 1)
        v += __shfl_down_sync(0xffffffffu, v, off);
    if (lane == 0) redw[wrp] = v;
    __syncthreads();
    const int bid = blockIdx.y * (NT / NFR) + blockIdx.x;
    if (tid == 0) {
        float s = redw[0];
        #pragma unroll
        for (int q = 1; q < 8; q++) s += redw[q];
        g_partial[bid] = s;
    }

    // ---- last block: deterministic global reduction ----
    __threadfence();
    if (tid == 0) {
        unsigned r = atomicAdd(&g_count, 1u);
        s_last = (r == NBLKS - 1) ? 1 : 0;
    }
    __syncthreads();
    if (s_last) {
        float s = 0.0f;
        for (int i = tid; i < NBLKS; i += NTHREADS) s += g_partial[i];
        #pragma unroll
        for (int off = 16; off > 0; off >>= 1)
            s += __shfl_down_sync(0xffffffffu, s, off);
        if (lane == 0) redw[wrp] = s;
        __syncthreads();
        if (tid == 0) {
            float s2 = redw[0];
            #pragma unroll
            for (int q = 1; q < 8; q++) s2 += redw[q];
            out[0] = s2 * (1.0f / (float)(BATCH * NBINS * NT));
            g_count = 0;                    // reset for next graph replay
        }
    }
}

extern "C" void kernel_launch(void* const* d_in, const int* in_sizes, int n_in,
                              void* d_out, int out_size) {
    const float* pred = (const float*)d_in[0];
    const float* tgt  = (const float*)d_in[1];
    float* out = (float*)d_out;
    dim3 grid(NT / NFR, BATCH);
    pam_kernel<<<grid, NTHREADS>>>(pred, tgt, out);
}

// round 8
// speedup vs baseline: 1.7112x; 1.0024x over previous
#include <cuda_runtime.h>
#include <math.h>

#define NFFT   512
#define HOP    480
#define NBINS  257
#define BATCH  8
#define LSIG   88200
#define NT     184
#define NFR    4                      // frames per block
#define NTHREADS 256
#define NBLKS  (BATCH * NT / NFR)     // 368 blocks
#define L2_10  3.3219280948873623f
#define BARKMID 12.37f

__device__ float g_partial[NBLKS];
__device__ unsigned int g_count = 0;

__device__ __forceinline__ float2 cadd(float2 a, float2 b) { return make_float2(a.x + b.x, a.y + b.y); }
__device__ __forceinline__ float2 csub(float2 a, float2 b) { return make_float2(a.x - b.x, a.y - b.y); }
__device__ __forceinline__ float2 cmul(float2 a, float2 b) {
    return make_float2(fmaf(a.x, b.x, -a.y * b.y), fmaf(a.x, b.y, a.y * b.x));
}

// 8-point DFT, natural in/out order
__device__ __forceinline__ void dft8(float2* x) {
    const float C = 0.70710678118654752f;
    float2 a0 = cadd(x[0], x[4]), a4 = csub(x[0], x[4]);
    float2 a2 = cadd(x[2], x[6]), a6 = csub(x[2], x[6]);
    float2 a1 = cadd(x[1], x[5]), a5 = csub(x[1], x[5]);
    float2 a3 = cadd(x[3], x[7]), a7 = csub(x[3], x[7]);
    float2 b0 = cadd(a0, a2), b2 = csub(a0, a2);
    float2 b1 = cadd(a1, a3), b3 = csub(a1, a3);
    float2 b4 = make_float2(a4.x + a6.y, a4.y - a6.x);
    float2 b6 = make_float2(a4.x - a6.y, a4.y + a6.x);
    float2 b5 = make_float2(a5.x + a7.y, a5.y - a7.x);
    float2 b7 = make_float2(a5.x - a7.y, a5.y + a7.x);
    x[0] = cadd(b0, b1);  x[4] = csub(b0, b1);
    x[2] = make_float2(b2.x + b3.y, b2.y - b3.x);
    x[6] = make_float2(b2.x - b3.y, b2.y + b3.x);
    float2 t5 = make_float2(C * (b5.x + b5.y), C * (b5.y - b5.x));
    x[1] = cadd(b4, t5);  x[5] = csub(b4, t5);
    float2 t7 = make_float2(C * (b7.y - b7.x), -C * (b7.x + b7.y));
    x[3] = cadd(b6, t7);  x[7] = csub(b6, t7);
}

#define PHYS(i) ((i) + ((i) >> 3))
// per-frame barrier: 64 threads (warps 2*sub, 2*sub+1), ids 1..4
#define BARF(id) asm volatile("bar.sync %0, %1;" :: "r"((id) + 1), "r"(64) : "memory")

__global__ __launch_bounds__(NTHREADS) void pam_kernel(
    const float* __restrict__ pred, const float* __restrict__ tgt,
    float* __restrict__ out)
{
    __shared__ float2 Zs[NFR][576];             // padded 512-pt complex, per frame
    __shared__ float aths[NBINS];
    __shared__ float cAs[NBINS], dAs[NBINS];    // 10^(+1.7(bark-M)), 10^(-1.7(bark-M))
    __shared__ float cBs[NBINS], dBs[NBINS];    // 10^(-2.7(bark-M)), 10^(+2.7(bark-M))
    __shared__ __align__(16) float pts[NFR][260];
    __shared__ float sAg[NFR], sBg[NFR];
    __shared__ float redw[8];
    __shared__ int   s_last;

    const int tid  = threadIdx.x;
    const int sub  = tid >> 6;             // frame within block (0..3)
    const int j    = tid & 63;             // thread within frame
    const int lane = tid & 31;
    const int wrp  = tid >> 5;             // 0..7
    const int fw   = wrp & 1;              // warp within frame

    const int t = NFR * blockIdx.x + sub;
    const int b = blockIdx.y;

    // ---- block-shared LUTs (all 4 frames share the same tables) ----
    for (int i = tid; i < NBINS; i += NTHREADS) {
        float freq = (float)i * (44100.0f / 512.0f);
        float r = freq * (1.0f / 7500.0f);
        float bark = 13.0f * atanf(0.00076f * freq) + 3.5f * atanf(r * r);
        float fk = fmaxf(freq, 1e-6f) * 1e-3f;
        float ath_db = 3.64f * __powf(fk, -0.8f)
                     - 6.5f * __expf(-0.6f * (fk - 3.3f) * (fk - 3.3f))
                     + 0.001f * fk * fk * fk * fk;
        ath_db = fminf(fmaxf(ath_db, -100.0f), 100.0f);
        aths[i] = fmaxf(exp2f(ath_db * (0.1f * L2_10)), 1e-12f);
        float d  = (bark - BARKMID) * L2_10;
        cAs[i] = exp2f( 1.7f * d);
        dAs[i] = exp2f(-1.7f * d);
        cBs[i] = exp2f(-2.7f * d);
        dBs[i] = exp2f( 2.7f * d);
    }

    // ---- load frame, natural order, inline window, reflect-padded ----
    const float* xp = pred + b * LSIG;
    const float* xt = tgt  + b * LSIG;
    const int tb = t * HOP - (NFFT / 2);
    #pragma unroll
    for (int h = 0; h < 8; h++) {
        int n = h * 64 + j;
        int g = tb + n;
        if (g < 0) g = -g;
        if (g >= LSIG) g = 2 * LSIG - 2 - g;
        float w = 0.5f * (1.0f - cospif((float)n * (1.0f / 256.0f)));
        Zs[sub][PHYS(n)] = make_float2(xp[g] * w, xt[g] * w);
    }
    __syncthreads();     // LUT visible to all + frame loaded

    // ---- pass 0: Lc=512, butterfly stride 64, twiddle W512^(j*r) ----
    {
        float2 x[8];
        #pragma unroll
        for (int m = 0; m < 8; m++) { int i = j + (m << 6); x[m] = Zs[sub][PHYS(i)]; }
        dft8(x);
        float s, c; sincospif((float)j * (1.0f / 256.0f), &s, &c);
        float2 w = make_float2(c, -s), wc = w;
        #pragma unroll
        for (int r = 1; r < 8; r++) { x[r] = cmul(x[r], wc); wc = cmul(wc, w); }
        #pragma unroll
        for (int r = 0; r < 8; r++) { int i = j + (r << 6); Zs[sub][PHYS(i)] = x[r]; }
    }
    BARF(sub);

    // ---- pass 1: Lc=64, stride 8, twiddle W64^(p*r) ----
    {
        int p = j & 7;
        int base = ((j >> 3) << 6) + p;
        float2 x[8];
        #pragma unroll
        for (int m = 0; m < 8; m++) { int i = base + (m << 3); x[m] = Zs[sub][PHYS(i)]; }
        dft8(x);
        float s, c; sincospif((float)p * (1.0f / 32.0f), &s, &c);
        float2 w = make_float2(c, -s), wc = w;
        #pragma unroll
        for (int r = 1; r < 8; r++) { x[r] = cmul(x[r], wc); wc = cmul(wc, w); }
        #pragma unroll
        for (int r = 0; r < 8; r++) { int i = base + (r << 3); Zs[sub][PHYS(i)] = x[r]; }
    }
    BARF(sub);

    // ---- pass 2: Lc=8, contiguous, no twiddle (phys = 9j+m) ----
    {
        float2 x[8];
        #pragma unroll
        for (int m = 0; m < 8; m++) x[m] = Zs[sub][9 * j + m];
        dft8(x);
        #pragma unroll
        for (int m = 0; m < 8; m++) Zs[sub][9 * j + m] = x[m];
    }
    BARF(sub);

    // ---- unpack both real spectra; bins 4j..4j+3 per thread ----
    float pp[4], pt[4];
    #pragma unroll
    for (int i = 0; i < 4; i++) {
        int k  = 4 * j + i;
        int pk = ((k & 7) << 6) | (k & 56) | (k >> 6);          // digit-reversed pos
        int kc = (NFFT - k) & (NFFT - 1);
        int pc = ((kc & 7) << 6) | (kc & 56) | (kc >> 6);
        float2 zk = Zs[sub][PHYS(pk)];
        float2 zc = Zs[sub][PHYS(pc)];
        float spr = zk.x + zc.x, spi = zk.y - zc.y;
        float str = zk.y + zc.y, sti = zc.x - zk.x;
        pp[i] = 0.25f * (spr * spr + spi * spi) + 1e-12f;
        pt[i] = 0.25f * (str * str + sti * sti) + 1e-12f;
    }
    *(float4*)&pts[sub][4 * j] = make_float4(pt[0], pt[1], pt[2], pt[3]);

    float pp6 = 0.f, pt6 = 0.f;
    if (j == 63) {                        // bin 256 lives at digit-reversed pos 4
        float2 z6 = Zs[sub][PHYS(4)];
        pp6 = z6.x * z6.x + 1e-12f;
        pt6 = z6.y * z6.y + 1e-12f;
        pts[sub][256] = pt6;
    }
    BARF(sub);

    // ---- tonal detection (power domain) + scaled linear masker terms ----
    float a[4], bb[4];
    float pprev = (j == 0) ? 3.4e38f : pts[sub][4 * j - 1];
    float pnext = pts[sub][4 * j + 4];
    #pragma unroll
    for (int i = 0; i < 4; i++) {
        int k = 4 * j + i;
        float p  = pt[i];
        float pl = (i == 0) ? pprev : pt[i - 1];
        float pr = (i == 3) ? pnext : pt[i + 1];
        bool tonal = (k >= 1) && (p > pl) && (p > pr) && (p >= 1e-4f);
        a[i]  = tonal ? p * cAs[k] : 0.0f;
        bb[i] = tonal ? p * cBs[k] : 0.0f;
    }

    // local prefix/suffix + thread aggregates
    float pa0 = a[0];
    float pa1 = fmaxf(pa0, a[1]);
    float pa2 = fmaxf(pa1, a[2]);
    float pa3 = fmaxf(pa2, a[3]);
    float sb3 = bb[3];
    float sb2 = fmaxf(sb3, bb[2]);
    float sb1 = fmaxf(sb2, bb[1]);
    float sb0 = fmaxf(sb1, bb[0]);

    // warp inclusive scan (forward) of thread aggregate pa3
    float inc = pa3;
    #pragma unroll
    for (int off = 1; off < 32; off <<= 1) {
        float o = __shfl_up_sync(0xffffffffu, inc, off);
        if (lane >= off) inc = fmaxf(inc, o);
    }
    float exA = __shfl_up_sync(0xffffffffu, inc, 1);
    if (lane == 0) exA = 0.0f;
    if (fw == 0 && lane == 31) sAg[sub] = inc;

    // warp reverse-inclusive scan of thread aggregate sb0
    float rinc = sb0;
    #pragma unroll
    for (int off = 1; off < 32; off <<= 1) {
        float o = __shfl_down_sync(0xffffffffu, rinc, off);
        if (lane + off < 32) rinc = fmaxf(rinc, o);
    }
    float exB = __shfl_down_sync(0xffffffffu, rinc, 1);
    if (lane == 31) exB = 0.0f;
    if (fw == 1 && lane == 0) sBg[sub] = rinc;
    BARF(sub);

    if (fw == 1) exA = fmaxf(exA, sAg[sub]);   // back warp sees front warp's total
    if (fw == 0) exB = fmaxf(exB, sBg[sub]);   // front warp sees back warp's total

    // ---- per-bin masking, weights, error ----
    float Apre[4] = { fmaxf(exA, pa0), fmaxf(exA, pa1), fmaxf(exA, pa2), fmaxf(exA, pa3) };
    float Bsuf[4] = { fmaxf(exB, sb0), fmaxf(exB, sb1), fmaxf(exB, sb2), fmaxf(exB, sb3) };

    float contrib = 0.0f;
    #pragma unroll
    for (int i = 0; i < 4; i++) {
        int k = 4 * j + i;
        float masking = fmaxf(Apre[i] * dAs[k], Bsuf[i] * dBs[k]);
        float combined = masking + aths[k];
        float w  = __log10f(pt[i] / (combined + 1e-12f) + 1.0f);
        float mp = sqrtf(pp[i]);
        float mt = sqrtf(pt[i]);
        float d  = mp - mt;
        contrib += w * d * d;
    }
    if (j == 63) {                          // bin 256: never tonal, A-side only
        float masking = Apre[3] * dAs[256];
        float combined = masking + aths[256];
        float w  = __log10f(pt6 / (combined + 1e-12f) + 1.0f);
        float mp = sqrtf(pp6);
        float mt = sqrtf(pt6);
        float d  = mp - mt;
        contrib += w * d * d;
    }

    // ---- block reduction (all 4 frames into one partial) ----
    float v = contrib;
    #pragma unroll
    for (int off = 16; off > 0; off >>= 1)
        v += __shfl_down_sync(0xffffffffu, v, off);
    if (lane == 0) redw[wrp] = v;
    __syncthreads();
    const int bid = blockIdx.y * (NT / NFR) + blockIdx.x;
    if (tid == 0) {
        float s = redw[0];
        #pragma unroll
        for (int q = 1; q < 8; q++) s += redw[q];
        g_partial[bid] = s;
    }

    // ---- last block: deterministic global reduction ----
    __threadfence();
    if (tid == 0) {
        unsigned r = atomicAdd(&g_count, 1u);
        s_last = (r == NBLKS - 1) ? 1 : 0;
    }
    __syncthreads();
    if (s_last) {
        float s = 0.0f;
        for (int i = tid; i < NBLKS; i += NTHREADS) s += g_partial[i];
        #pragma unroll
        for (int off = 16; off > 0; off >>= 1)
            s += __shfl_down_sync(0xffffffffu, s, off);
        if (lane == 0) redw[wrp] = s;
        __syncthreads();
        if (tid == 0) {
            float s2 = redw[0];
            #pragma unroll
            for (int q = 1; q < 8; q++) s2 += redw[q];
            out[0] = s2 * (1.0f / (float)(BATCH * NBINS * NT));
            g_count = 0;                    // reset for next graph replay
        }
    }
}

extern "C" void kernel_launch(void* const* d_in, const int* in_sizes, int n_in,
                              void* d_out, int out_size) {
    const float* pred = (const float*)d_in[0];
    const float* tgt  = (const float*)d_in[1];
    float* out = (float*)d_out;
    dim3 grid(NT / NFR, BATCH);
    pam_kernel<<<grid, NTHREADS>>>(pred, tgt, out);
}